// round 10
// baseline (speedup 1.0000x reference)
#include <cuda_runtime.h>

// CEHawkesProcess — Hawkes NLL. 2 launches: parallel prep + high-occupancy main.
// Main = R4-style per-item table loads (L1-resident slices) with td pre-baked,
// 2-way unroll, __launch_bounds__(256,7) to reach ~7 blocks/SM occupancy.
// Inputs (metadata order):
// 0 event_times f32[B*L], 1 event_types i32[B*L], 2 event_categories i32[B*L],
// 3 T (scalar), 4 type_emb f32[NT*E], 5 cat_emb f32[NC*E], 6 a f32[NT*E],
// 7 b f32[NC*E], 8 A f32[NT*NT*E], 9 P f32[NT*NT*E], 10 Bm f32[NC*NC*E],
// 11 Q f32[NC*NC*E].  Output: scalar f32.

namespace {
constexpr int NTY = 50;
constexpr int NCA = 20;
constexpr int EMB = 64;
constexpr int BSZ = 4;
constexpr int SEQ = 256;
constexpr float NL2E = -1.4426950408889634f;  // -log2(e)

// main grid: heavy (full-scan) blocks first, then events in descending-i order
constexpr int HT_BLKS = BSZ * NTY;                        // 200
constexpr int HC_BLKS = BSZ;                              // 4
constexpr int EV_BLKS = BSZ * SEQ;                        // 1024
constexpr int MAIN_BLKS = HT_BLKS + HC_BLKS + EV_BLKS;    // 1228

// prep grid (vectorized float4)
constexpr int TT_BLKS = (NTY * NTY + 15) / 16;            // 157
constexpr int TC_BLKS = (NCA * NCA + 15) / 16;            // 25
constexpr int FB_BLKS = (NTY * NCA + 7) / 8;              // 125
constexpr int BA_BLKS = (NTY + 7) / 8;                    // 7
constexpr int FE_BLKS = 4;
constexpr int PREP_BLKS = TT_BLKS + TC_BLKS + FB_BLKS + BA_BLKS + FE_BLKS + 1;  // 319
}

// Tables, [target][source][e]: consumer block reads a contiguous slice.
__device__ float2 g_TT[NTY * NTY * EMB];   // {f[t]A[k,t]f[k], NL2E*f[t]P[k,t]f[k]}
__device__ float2 g_TC[NCA * NCA * EMB];   // {g[c2]Bm[c1,c2]g[c1], NL2E*g[c2]Q[c1,c2]g[c1]}
__device__ float g_FEmb[NTY * EMB];        // copy of type_emb
__device__ float g_BA[NTY];                // sum_e f*a
__device__ float g_SP[NTY];                // sum_e softplus(f*a)
__device__ float g_FB[NTY * NCA];          // sum_e f[t]*b[c]
__device__ float g_Fsum[EMB];              // sum_t f[t,e]
__device__ float g_SFB[NCA];               // sum_t FB[t,c]
__device__ float g_Sba, g_I0;
__device__ float g_part[MAIN_BLKS];
__device__ unsigned g_done;                // zero-init; finalizer resets (replay-safe)

struct alignas(16) Ent { float td; int ko; int co; int pad; };

__device__ __forceinline__ float fast_exp2(float x) {
    float r;
    asm("ex2.approx.ftz.f32 %0, %1;" : "=f"(r) : "f"(x));
    return r;
}

__device__ __forceinline__ float softplusf(float x) {
    return fmaxf(x, 0.f) + log1pf(expf(-fabsf(x)));
}

// T may arrive as int32 (value 128) or float32 bits; disambiguate.
__device__ __forceinline__ float readT(const void* p) {
    int v = *(const int*)p;
    return (v > 0 && v < (1 << 24)) ? (float)v : __int_as_float(v);
}

__device__ __forceinline__ float warp_reduce(float v) {
    #pragma unroll
    for (int o = 16; o; o >>= 1) v += __shfl_down_sync(0xffffffffu, v, o);
    return v;
}

__device__ __forceinline__ float block_reduce_256(float v, float* sred) {
    v = warp_reduce(v);
    int tid = threadIdx.x;
    if ((tid & 31) == 0) sred[tid >> 5] = v;
    __syncthreads();
    float r = 0.f;
    if (tid == 0) {
        #pragma unroll
        for (int w = 0; w < 8; w++) r += sred[w];
    }
    return r;
}

// ======================= prep: tables + scalars + femb, all parallel =========
__global__ void __launch_bounds__(256) k_prep(
    const float* __restrict__ f, const float* __restrict__ g,
    const float* __restrict__ a, const float* __restrict__ b,
    const float* __restrict__ A, const float* __restrict__ P,
    const float* __restrict__ Bm, const float* __restrict__ Q) {
    int bid = blockIdx.x;
    int tid = threadIdx.x;

    if (bid < TT_BLKS) {
        int p = bid * 16 + (tid >> 4);          // p = t*NTY + k (write row)
        if (p < NTY * NTY) {
            int e = (tid & 15) << 2;
            int t = p / NTY, k = p - t * NTY;
            int rd = (k * NTY + t) * EMB + e;   // A/P stored [k][t][e]
            float4 Av = *(const float4*)(A + rd);
            float4 Pv = *(const float4*)(P + rd);
            float4 ft = *(const float4*)(f + t * EMB + e);
            float4 fk = *(const float4*)(f + k * EMB + e);
            float w0 = ft.x * fk.x, w1 = ft.y * fk.y;
            float w2 = ft.z * fk.z, w3 = ft.w * fk.w;
            float4* dst = (float4*)(g_TT + p * EMB + e);
            dst[0] = make_float4(w0 * Av.x, NL2E * w0 * Pv.x, w1 * Av.y, NL2E * w1 * Pv.y);
            dst[1] = make_float4(w2 * Av.z, NL2E * w2 * Pv.z, w3 * Av.w, NL2E * w3 * Pv.w);
        }
        return;
    }
    bid -= TT_BLKS;
    if (bid < TC_BLKS) {
        int p = bid * 16 + (tid >> 4);          // p = c2*NCA + c1 (write row)
        if (p < NCA * NCA) {
            int e = (tid & 15) << 2;
            int c2 = p / NCA, c1 = p - c2 * NCA;
            int rd = (c1 * NCA + c2) * EMB + e; // Bm/Q stored [c1][c2][e]
            float4 Bv = *(const float4*)(Bm + rd);
            float4 Qv = *(const float4*)(Q + rd);
            float4 g2 = *(const float4*)(g + c2 * EMB + e);
            float4 g1 = *(const float4*)(g + c1 * EMB + e);
            float w0 = g2.x * g1.x, w1 = g2.y * g1.y;
            float w2 = g2.z * g1.z, w3 = g2.w * g1.w;
            float4* dst = (float4*)(g_TC + p * EMB + e);
            dst[0] = make_float4(w0 * Bv.x, NL2E * w0 * Qv.x, w1 * Bv.y, NL2E * w1 * Qv.y);
            dst[1] = make_float4(w2 * Bv.z, NL2E * w2 * Qv.z, w3 * Bv.w, NL2E * w3 * Qv.w);
        }
        return;
    }
    bid -= TC_BLKS;
    if (bid < FB_BLKS) {
        int w = tid >> 5, lane = tid & 31;
        int idx = bid * 8 + w;
        if (idx < NTY * NCA) {
            int t = idx / NCA, c = idx - t * NCA;
            float s = f[t * EMB + lane] * b[c * EMB + lane]
                    + f[t * EMB + lane + 32] * b[c * EMB + lane + 32];
            s = warp_reduce(s);
            if (lane == 0) g_FB[idx] = s;
        }
        return;
    }
    bid -= FB_BLKS;
    if (bid < BA_BLKS) {
        int w = tid >> 5, lane = tid & 31;
        int t = bid * 8 + w;
        if (t < NTY) {
            float x0 = f[t * EMB + lane] * a[t * EMB + lane];
            float x1 = f[t * EMB + lane + 32] * a[t * EMB + lane + 32];
            float ba = warp_reduce(x0 + x1);
            float sp = warp_reduce(softplusf(x0) + softplusf(x1));
            if (lane == 0) { g_BA[t] = ba; g_SP[t] = sp; }
        }
        return;
    }
    bid -= BA_BLKS;
    if (bid < FE_BLKS) {
        int idx4 = bid * 256 + tid;
        if (idx4 < (NTY * EMB) / 4)
            ((float4*)g_FEmb)[idx4] = ((const float4*)f)[idx4];
        return;
    }
    // ---- final scalar block: Fsum, SFB, Sba, I0 ----
    __shared__ float fs_sh[EMB];
    __shared__ float sred1[8];
    __shared__ float sred2[8];
    if (tid < EMB) {
        float s = 0.f;
        #pragma unroll
        for (int t = 0; t < NTY; t++) s += f[t * EMB + tid];
        g_Fsum[tid] = s;
        fs_sh[tid] = s;
    }
    float sba = 0.f, i0 = 0.f;
    for (int idx = tid; idx < NTY * EMB; idx += 256) {
        float x = f[idx] * a[idx];
        sba += x;
        i0 += softplusf(x);
    }
    sba = warp_reduce(sba);
    i0 = warp_reduce(i0);
    if ((tid & 31) == 0) { sred1[tid >> 5] = sba; sred2[tid >> 5] = i0; }
    __syncthreads();
    if (tid == 0) {
        float s = 0.f, s2 = 0.f;
        #pragma unroll
        for (int w = 0; w < 8; w++) { s += sred1[w]; s2 += sred2[w]; }
        g_Sba = s;
        g_I0 = s2;
    }
    {
        int w = tid >> 5, lane = tid & 31;
        for (int c = w; c < NCA; c += 8) {
            float s = fs_sh[lane] * b[c * EMB + lane]
                    + fs_sh[lane + 32] * b[c * EMB + lane + 32];
            s = warp_reduce(s);
            if (lane == 0) g_SFB[c] = s;
        }
    }
}

// ======================= main: high-occupancy per-item scan ==================
__global__ void __launch_bounds__(256, 7) k_main(
    const float* __restrict__ times, const int* __restrict__ types,
    const int* __restrict__ cats, const void* __restrict__ Tp,
    float* __restrict__ out) {
    int bid = blockIdx.x;
    int tid = threadIdx.x;
    __shared__ Ent sh[SEQ];
    __shared__ float sred[8];
    __shared__ double dred[8];
    __shared__ int sh_last;

    int e = tid & (EMB - 1);
    int ch = tid >> 6;  // 0..3
    float partial = 0.f;

    if (bid < HT_BLKS) {
        // ---- horizon type channel: (b, t); td = Tf - t_s baked in ----
        int bb = bid / NTY;
        int t = bid - bb * NTY;
        float Tf = readT(Tp);
        const float* ts = times + bb * SEQ;
        const int* ty = types + bb * SEQ;
        float tlast = ts[SEQ - 1];
        for (int s = tid; s < SEQ; s += 256) {
            Ent en; en.td = Tf - ts[s]; en.ko = ty[s] * EMB; en.co = 0; en.pad = 0;
            sh[s] = en;
        }
        __syncthreads();
        const float2* __restrict__ ttb = g_TT + (size_t)t * (NTY * EMB) + e;
        float a0 = 0.f, a1 = 0.f;
        #pragma unroll 4
        for (int s = ch; s < SEQ; s += 8) {
            Ent e0 = sh[s], e1 = sh[s + 4];
            float2 w0 = __ldg(ttb + e0.ko);
            float2 w1 = __ldg(ttb + e1.ko);
            a0 = fmaf(w0.x, fast_exp2(w0.y * e0.td), a0);
            a1 = fmaf(w1.x, fast_exp2(w1.y * e1.td), a1);
        }
        float total = block_reduce_256(a0 + a1, sred);
        if (tid == 0) partial = total * (Tf - tlast);
    } else if (bid < HT_BLKS + HC_BLKS) {
        // ---- horizon category channel: b ----
        int bb = bid - HT_BLKS;
        float Tf = readT(Tp);
        const float* ts = times + bb * SEQ;
        const int* ct = cats + bb * SEQ;
        float tlast = ts[SEQ - 1];
        for (int s = tid; s < SEQ; s += 256) {
            Ent en; en.td = Tf - ts[s]; en.co = ct[s] * EMB; en.ko = 0; en.pad = 0;
            sh[s] = en;
        }
        __syncthreads();
        int lcL = ct[SEQ - 1];
        const float2* __restrict__ tcb = g_TC + (size_t)lcL * (NCA * EMB) + e;
        float a0 = 0.f, a1 = 0.f;
        #pragma unroll 4
        for (int s = ch; s < SEQ; s += 8) {
            Ent e0 = sh[s], e1 = sh[s + 4];
            float2 w0 = __ldg(tcb + e0.co);
            float2 w1 = __ldg(tcb + e1.co);
            a0 = fmaf(w0.x, fast_exp2(w0.y * e0.td), a0);
            a1 = fmaf(w1.x, fast_exp2(w1.y * e1.td), a1);
        }
        float acc = (a0 + a1) * g_Fsum[e];
        float total = block_reduce_256(acc, sred);
        if (tid == 0) partial = total * (Tf - tlast);
    } else {
        // ---- per-event log-likelihood (descending-i order; heaviest first) ----
        int local = bid - HT_BLKS - HC_BLKS;
        int i = (SEQ - 1) - (local >> 2);
        int bb = local & 3;
        const float* ts = times + bb * SEQ;
        const int* ty = types + bb * SEQ;
        const int* ct = cats + bb * SEQ;
        int ti = ty[i];
        float t_i = ts[i];

        if (i == 0) {
            if (tid == 0 && t_i >= 0.f) {
                float lam = g_SP[ti];
                partial = -(logf(lam + 1e-16f) + lam);
            }
        } else {
            for (int s = tid; s < i; s += 256) {
                Ent en;
                en.td = t_i - ts[s];
                en.ko = ty[s] * EMB;
                en.co = ct[s] * EMB;
                en.pad = 0;
                sh[s] = en;
            }
            __syncthreads();

            int lc = ct[i - 1];
            const float2* __restrict__ ttb = g_TT + (size_t)ti * (NTY * EMB) + e;
            const float2* __restrict__ tcb = g_TC + (size_t)lc * (NCA * EMB) + e;
            float aT0 = 0.f, aT1 = 0.f, aC0 = 0.f, aC1 = 0.f;
            int s = ch;
            for (; s + 4 < i; s += 8) {
                Ent e0 = sh[s], e1 = sh[s + 4];
                float2 t0 = __ldg(ttb + e0.ko);
                float2 c0 = __ldg(tcb + e0.co);
                float2 t1 = __ldg(ttb + e1.ko);
                float2 c1 = __ldg(tcb + e1.co);
                aT0 = fmaf(t0.x, fast_exp2(t0.y * e0.td), aT0);
                aC0 = fmaf(c0.x, fast_exp2(c0.y * e0.td), aC0);
                aT1 = fmaf(t1.x, fast_exp2(t1.y * e1.td), aT1);
                aC1 = fmaf(c1.x, fast_exp2(c1.y * e1.td), aC1);
            }
            if (s < i) {
                Ent e0 = sh[s];
                float2 t0 = __ldg(ttb + e0.ko);
                float2 c0 = __ldg(tcb + e0.co);
                aT0 = fmaf(t0.x, fast_exp2(t0.y * e0.td), aT0);
                aC0 = fmaf(c0.x, fast_exp2(c0.y * e0.td), aC0);
            }
            float fev = g_FEmb[ti * EMB + e];
            float acc = (aT0 + aT1) + fev * (aC0 + aC1);
            float total = block_reduce_256(acc, sred);
            if (tid == 0 && t_i >= 0.f) {
                float lam = g_BA[ti] + g_FB[ti * NCA + lc] + total;
                partial = -(logf(lam + 1e-16f) + lam);
            }
        }
    }

    // ---- publish partial + grid-completion finalizer ----
    if (tid == 0) {
        g_part[bid] = partial;
        __threadfence();
        unsigned n = atomicAdd(&g_done, 1u);
        sh_last = (n == (unsigned)(MAIN_BLKS - 1)) ? 1 : 0;
        if (sh_last) __threadfence();
    }
    __syncthreads();
    if (sh_last) {
        double v = 0.0;
        for (int idx = tid; idx < MAIN_BLKS; idx += 256) v += (double)g_part[idx];
        #pragma unroll
        for (int o = 16; o; o >>= 1) v += __shfl_down_sync(0xffffffffu, v, o);
        if ((tid & 31) == 0) dred[tid >> 5] = v;
        __syncthreads();
        if (tid == 0) {
            double r = 0.0;
            #pragma unroll
            for (int w = 0; w < 8; w++) r += dred[w];
            float Tf = readT(Tp);
            for (int b2 = 0; b2 < BSZ; b2++) {
                int lcL = cats[b2 * SEQ + SEQ - 1];
                float tlast = times[b2 * SEQ + SEQ - 1];
                float t0 = times[b2 * SEQ];
                r += (double)((g_Sba + g_SFB[lcL]) * (Tf - tlast) + g_I0 * t0);
            }
            out[0] = (float)r;
            g_done = 0u;  // reset for next replay
        }
    }
}

extern "C" void kernel_launch(void* const* d_in, const int* in_sizes, int n_in,
                              void* d_out, int out_size) {
    const float* times = (const float*)d_in[0];
    const int* types = (const int*)d_in[1];
    const int* cats = (const int*)d_in[2];
    const void* Tp = d_in[3];
    const float* type_emb = (const float*)d_in[4];
    const float* cat_emb = (const float*)d_in[5];
    const float* a = (const float*)d_in[6];
    const float* b = (const float*)d_in[7];
    const float* A = (const float*)d_in[8];
    const float* P = (const float*)d_in[9];
    const float* Bm = (const float*)d_in[10];
    const float* Q = (const float*)d_in[11];
    float* out = (float*)d_out;

    k_prep<<<PREP_BLKS, 256>>>(type_emb, cat_emb, a, b, A, P, Bm, Q);
    k_main<<<MAIN_BLKS, 256>>>(times, types, cats, Tp, out);
}

// round 11
// speedup vs baseline: 1.1633x; 1.1633x over previous
#include <cuda_runtime.h>
#include <cuda_fp16.h>

// CEHawkesProcess — Hawkes NLL. 2 launches: parallel prep + main.
// Tables stored as __half2 {w, r}: halves per-target slice to ~18KB so all
// resident blocks' table slices fit in L1 (228KB) -> per-item loads L1-hit.
// Inputs (metadata order):
// 0 event_times f32[B*L], 1 event_types i32[B*L], 2 event_categories i32[B*L],
// 3 T (scalar), 4 type_emb f32[NT*E], 5 cat_emb f32[NC*E], 6 a f32[NT*E],
// 7 b f32[NC*E], 8 A f32[NT*NT*E], 9 P f32[NT*NT*E], 10 Bm f32[NC*NC*E],
// 11 Q f32[NC*NC*E].  Output: scalar f32.

namespace {
constexpr int NTY = 50;
constexpr int NCA = 20;
constexpr int EMB = 64;
constexpr int BSZ = 4;
constexpr int SEQ = 256;
constexpr float NL2E = -1.4426950408889634f;  // -log2(e)

// main grid: heavy (full-scan) blocks first, then events in descending-i order
constexpr int HT_BLKS = BSZ * NTY;                        // 200
constexpr int HC_BLKS = BSZ;                              // 4
constexpr int EV_BLKS = BSZ * SEQ;                        // 1024
constexpr int MAIN_BLKS = HT_BLKS + HC_BLKS + EV_BLKS;    // 1228

// prep grid
constexpr int TT_BLKS = (NTY * NTY + 15) / 16;            // 157
constexpr int TC_BLKS = (NCA * NCA + 15) / 16;            // 25
constexpr int FB_BLKS = (NTY * NCA + 7) / 8;              // 125
constexpr int BA_BLKS = (NTY + 7) / 8;                    // 7
constexpr int FE_BLKS = 4;
constexpr int PREP_BLKS = TT_BLKS + TC_BLKS + FB_BLKS + BA_BLKS + FE_BLKS + 1;  // 319
}

// Tables, [target][source][e], fp16-packed {w, r} per entry.
__device__ __half2 g_TTh[NTY * NTY * EMB];  // {f[t]A[k,t]f[k], NL2E*f[t]P[k,t]f[k]}
__device__ __half2 g_TCh[NCA * NCA * EMB];  // {g[c2]Bm g[c1], NL2E*g[c2]Q g[c1]}
__device__ float g_FEmb[NTY * EMB];        // copy of type_emb
__device__ float g_BA[NTY];                // sum_e f*a
__device__ float g_SP[NTY];                // sum_e softplus(f*a)
__device__ float g_FB[NTY * NCA];          // sum_e f[t]*b[c]
__device__ float g_Fsum[EMB];              // sum_t f[t,e]
__device__ float g_SFB[NCA];               // sum_t FB[t,c]
__device__ float g_Sba, g_I0;
__device__ float g_part[MAIN_BLKS];
__device__ unsigned g_done;                // zero-init; finalizer resets (replay-safe)

struct alignas(16) Ent { float td; int ko; int co; int pad; };

__device__ __forceinline__ float fast_exp2(float x) {
    float r;
    asm("ex2.approx.ftz.f32 %0, %1;" : "=f"(r) : "f"(x));
    return r;
}

__device__ __forceinline__ float softplusf(float x) {
    return fmaxf(x, 0.f) + log1pf(expf(-fabsf(x)));
}

// T may arrive as int32 (value 128) or float32 bits; disambiguate.
__device__ __forceinline__ float readT(const void* p) {
    int v = *(const int*)p;
    return (v > 0 && v < (1 << 24)) ? (float)v : __int_as_float(v);
}

__device__ __forceinline__ float warp_reduce(float v) {
    #pragma unroll
    for (int o = 16; o; o >>= 1) v += __shfl_down_sync(0xffffffffu, v, o);
    return v;
}

__device__ __forceinline__ float block_reduce_256(float v, float* sred) {
    v = warp_reduce(v);
    int tid = threadIdx.x;
    if ((tid & 31) == 0) sred[tid >> 5] = v;
    __syncthreads();
    float r = 0.f;
    if (tid == 0) {
        #pragma unroll
        for (int w = 0; w < 8; w++) r += sred[w];
    }
    return r;
}

// ======================= prep: tables + scalars + femb, all parallel =========
__global__ void __launch_bounds__(256) k_prep(
    const float* __restrict__ f, const float* __restrict__ g,
    const float* __restrict__ a, const float* __restrict__ b,
    const float* __restrict__ A, const float* __restrict__ P,
    const float* __restrict__ Bm, const float* __restrict__ Q) {
    int bid = blockIdx.x;
    int tid = threadIdx.x;

    if (bid < TT_BLKS) {
        int p = bid * 16 + (tid >> 4);          // p = t*NTY + k (write row)
        if (p < NTY * NTY) {
            int e = (tid & 15) << 2;
            int t = p / NTY, k = p - t * NTY;
            int rd = (k * NTY + t) * EMB + e;   // A/P stored [k][t][e]
            float4 Av = *(const float4*)(A + rd);
            float4 Pv = *(const float4*)(P + rd);
            float4 ft = *(const float4*)(f + t * EMB + e);
            float4 fk = *(const float4*)(f + k * EMB + e);
            float w0 = ft.x * fk.x, w1 = ft.y * fk.y;
            float w2 = ft.z * fk.z, w3 = ft.w * fk.w;
            __half2 h0 = __floats2half2_rn(w0 * Av.x, NL2E * w0 * Pv.x);
            __half2 h1 = __floats2half2_rn(w1 * Av.y, NL2E * w1 * Pv.y);
            __half2 h2 = __floats2half2_rn(w2 * Av.z, NL2E * w2 * Pv.z);
            __half2 h3 = __floats2half2_rn(w3 * Av.w, NL2E * w3 * Pv.w);
            uint4 pkt;
            pkt.x = *(unsigned*)&h0; pkt.y = *(unsigned*)&h1;
            pkt.z = *(unsigned*)&h2; pkt.w = *(unsigned*)&h3;
            *(uint4*)(g_TTh + p * EMB + e) = pkt;
        }
        return;
    }
    bid -= TT_BLKS;
    if (bid < TC_BLKS) {
        int p = bid * 16 + (tid >> 4);          // p = c2*NCA + c1 (write row)
        if (p < NCA * NCA) {
            int e = (tid & 15) << 2;
            int c2 = p / NCA, c1 = p - c2 * NCA;
            int rd = (c1 * NCA + c2) * EMB + e; // Bm/Q stored [c1][c2][e]
            float4 Bv = *(const float4*)(Bm + rd);
            float4 Qv = *(const float4*)(Q + rd);
            float4 g2 = *(const float4*)(g + c2 * EMB + e);
            float4 g1 = *(const float4*)(g + c1 * EMB + e);
            float w0 = g2.x * g1.x, w1 = g2.y * g1.y;
            float w2 = g2.z * g1.z, w3 = g2.w * g1.w;
            __half2 h0 = __floats2half2_rn(w0 * Bv.x, NL2E * w0 * Qv.x);
            __half2 h1 = __floats2half2_rn(w1 * Bv.y, NL2E * w1 * Qv.y);
            __half2 h2 = __floats2half2_rn(w2 * Bv.z, NL2E * w2 * Qv.z);
            __half2 h3 = __floats2half2_rn(w3 * Bv.w, NL2E * w3 * Qv.w);
            uint4 pkt;
            pkt.x = *(unsigned*)&h0; pkt.y = *(unsigned*)&h1;
            pkt.z = *(unsigned*)&h2; pkt.w = *(unsigned*)&h3;
            *(uint4*)(g_TCh + p * EMB + e) = pkt;
        }
        return;
    }
    bid -= TC_BLKS;
    if (bid < FB_BLKS) {
        int w = tid >> 5, lane = tid & 31;
        int idx = bid * 8 + w;
        if (idx < NTY * NCA) {
            int t = idx / NCA, c = idx - t * NCA;
            float s = f[t * EMB + lane] * b[c * EMB + lane]
                    + f[t * EMB + lane + 32] * b[c * EMB + lane + 32];
            s = warp_reduce(s);
            if (lane == 0) g_FB[idx] = s;
        }
        return;
    }
    bid -= FB_BLKS;
    if (bid < BA_BLKS) {
        int w = tid >> 5, lane = tid & 31;
        int t = bid * 8 + w;
        if (t < NTY) {
            float x0 = f[t * EMB + lane] * a[t * EMB + lane];
            float x1 = f[t * EMB + lane + 32] * a[t * EMB + lane + 32];
            float ba = warp_reduce(x0 + x1);
            float sp = warp_reduce(softplusf(x0) + softplusf(x1));
            if (lane == 0) { g_BA[t] = ba; g_SP[t] = sp; }
        }
        return;
    }
    bid -= BA_BLKS;
    if (bid < FE_BLKS) {
        int idx4 = bid * 256 + tid;
        if (idx4 < (NTY * EMB) / 4)
            ((float4*)g_FEmb)[idx4] = ((const float4*)f)[idx4];
        return;
    }
    // ---- final scalar block: Fsum, SFB, Sba, I0 ----
    __shared__ float fs_sh[EMB];
    __shared__ float sred1[8];
    __shared__ float sred2[8];
    if (tid < EMB) {
        float s = 0.f;
        #pragma unroll
        for (int t = 0; t < NTY; t++) s += f[t * EMB + tid];
        g_Fsum[tid] = s;
        fs_sh[tid] = s;
    }
    float sba = 0.f, i0 = 0.f;
    for (int idx = tid; idx < NTY * EMB; idx += 256) {
        float x = f[idx] * a[idx];
        sba += x;
        i0 += softplusf(x);
    }
    sba = warp_reduce(sba);
    i0 = warp_reduce(i0);
    if ((tid & 31) == 0) { sred1[tid >> 5] = sba; sred2[tid >> 5] = i0; }
    __syncthreads();
    if (tid == 0) {
        float s = 0.f, s2 = 0.f;
        #pragma unroll
        for (int w = 0; w < 8; w++) { s += sred1[w]; s2 += sred2[w]; }
        g_Sba = s;
        g_I0 = s2;
    }
    {
        int w = tid >> 5, lane = tid & 31;
        for (int c = w; c < NCA; c += 8) {
            float s = fs_sh[lane] * b[c * EMB + lane]
                    + fs_sh[lane + 32] * b[c * EMB + lane + 32];
            s = warp_reduce(s);
            if (lane == 0) g_SFB[c] = s;
        }
    }
}

// ======================= main: fp16-table per-item scan ======================
__device__ __forceinline__ float2 ldh2(const __half2* p) {
    __half2 h = __ldg(p);
    return __half22float2(h);
}

__global__ void __launch_bounds__(256) k_main(
    const float* __restrict__ times, const int* __restrict__ types,
    const int* __restrict__ cats, const void* __restrict__ Tp,
    float* __restrict__ out) {
    int bid = blockIdx.x;
    int tid = threadIdx.x;
    __shared__ Ent sh[SEQ];
    __shared__ float sred[8];
    __shared__ double dred[8];
    __shared__ int sh_last;

    int e = tid & (EMB - 1);
    int ch = tid >> 6;  // 0..3
    float partial = 0.f;

    if (bid < HT_BLKS) {
        // ---- horizon type channel: (b, t); td = Tf - t_s baked in ----
        int bb = bid / NTY;
        int t = bid - bb * NTY;
        float Tf = readT(Tp);
        const float* ts = times + bb * SEQ;
        const int* ty = types + bb * SEQ;
        float tlast = ts[SEQ - 1];
        for (int s = tid; s < SEQ; s += 256) {
            Ent en; en.td = Tf - ts[s]; en.ko = ty[s] * EMB; en.co = 0; en.pad = 0;
            sh[s] = en;
        }
        __syncthreads();
        const __half2* __restrict__ ttb = g_TTh + (size_t)t * (NTY * EMB) + e;
        float a0 = 0.f, a1 = 0.f, a2 = 0.f, a3 = 0.f;
        #pragma unroll 2
        for (int s = ch; s < SEQ; s += 16) {
            Ent e0 = sh[s], e1 = sh[s + 4], e2 = sh[s + 8], e3 = sh[s + 12];
            float2 w0 = ldh2(ttb + e0.ko);
            float2 w1 = ldh2(ttb + e1.ko);
            float2 w2 = ldh2(ttb + e2.ko);
            float2 w3 = ldh2(ttb + e3.ko);
            a0 = fmaf(w0.x, fast_exp2(w0.y * e0.td), a0);
            a1 = fmaf(w1.x, fast_exp2(w1.y * e1.td), a1);
            a2 = fmaf(w2.x, fast_exp2(w2.y * e2.td), a2);
            a3 = fmaf(w3.x, fast_exp2(w3.y * e3.td), a3);
        }
        float total = block_reduce_256((a0 + a1) + (a2 + a3), sred);
        if (tid == 0) partial = total * (Tf - tlast);
    } else if (bid < HT_BLKS + HC_BLKS) {
        // ---- horizon category channel: b ----
        int bb = bid - HT_BLKS;
        float Tf = readT(Tp);
        const float* ts = times + bb * SEQ;
        const int* ct = cats + bb * SEQ;
        float tlast = ts[SEQ - 1];
        for (int s = tid; s < SEQ; s += 256) {
            Ent en; en.td = Tf - ts[s]; en.co = ct[s] * EMB; en.ko = 0; en.pad = 0;
            sh[s] = en;
        }
        __syncthreads();
        int lcL = ct[SEQ - 1];
        const __half2* __restrict__ tcb = g_TCh + (size_t)lcL * (NCA * EMB) + e;
        float a0 = 0.f, a1 = 0.f, a2 = 0.f, a3 = 0.f;
        #pragma unroll 2
        for (int s = ch; s < SEQ; s += 16) {
            Ent e0 = sh[s], e1 = sh[s + 4], e2 = sh[s + 8], e3 = sh[s + 12];
            float2 w0 = ldh2(tcb + e0.co);
            float2 w1 = ldh2(tcb + e1.co);
            float2 w2 = ldh2(tcb + e2.co);
            float2 w3 = ldh2(tcb + e3.co);
            a0 = fmaf(w0.x, fast_exp2(w0.y * e0.td), a0);
            a1 = fmaf(w1.x, fast_exp2(w1.y * e1.td), a1);
            a2 = fmaf(w2.x, fast_exp2(w2.y * e2.td), a2);
            a3 = fmaf(w3.x, fast_exp2(w3.y * e3.td), a3);
        }
        float acc = ((a0 + a1) + (a2 + a3)) * g_Fsum[e];
        float total = block_reduce_256(acc, sred);
        if (tid == 0) partial = total * (Tf - tlast);
    } else {
        // ---- per-event log-likelihood (descending-i order; heaviest first) ----
        int local = bid - HT_BLKS - HC_BLKS;
        int i = (SEQ - 1) - (local >> 2);
        int bb = local & 3;
        const float* ts = times + bb * SEQ;
        const int* ty = types + bb * SEQ;
        const int* ct = cats + bb * SEQ;
        int ti = ty[i];
        float t_i = ts[i];

        if (i == 0) {
            if (tid == 0 && t_i >= 0.f) {
                float lam = g_SP[ti];
                partial = -(logf(lam + 1e-16f) + lam);
            }
        } else {
            for (int s = tid; s < i; s += 256) {
                Ent en;
                en.td = t_i - ts[s];
                en.ko = ty[s] * EMB;
                en.co = ct[s] * EMB;
                en.pad = 0;
                sh[s] = en;
            }
            __syncthreads();

            int lc = ct[i - 1];
            const __half2* __restrict__ ttb = g_TTh + (size_t)ti * (NTY * EMB) + e;
            const __half2* __restrict__ tcb = g_TCh + (size_t)lc * (NCA * EMB) + e;
            float aT0 = 0.f, aT1 = 0.f, aT2 = 0.f, aT3 = 0.f;
            float aC0 = 0.f, aC1 = 0.f, aC2 = 0.f, aC3 = 0.f;
            int s = ch;
            for (; s + 12 < i; s += 16) {
                Ent e0 = sh[s], e1 = sh[s + 4], e2 = sh[s + 8], e3 = sh[s + 12];
                float2 t0 = ldh2(ttb + e0.ko);
                float2 c0 = ldh2(tcb + e0.co);
                float2 t1 = ldh2(ttb + e1.ko);
                float2 c1 = ldh2(tcb + e1.co);
                float2 t2 = ldh2(ttb + e2.ko);
                float2 c2 = ldh2(tcb + e2.co);
                float2 t3 = ldh2(ttb + e3.ko);
                float2 c3 = ldh2(tcb + e3.co);
                aT0 = fmaf(t0.x, fast_exp2(t0.y * e0.td), aT0);
                aC0 = fmaf(c0.x, fast_exp2(c0.y * e0.td), aC0);
                aT1 = fmaf(t1.x, fast_exp2(t1.y * e1.td), aT1);
                aC1 = fmaf(c1.x, fast_exp2(c1.y * e1.td), aC1);
                aT2 = fmaf(t2.x, fast_exp2(t2.y * e2.td), aT2);
                aC2 = fmaf(c2.x, fast_exp2(c2.y * e2.td), aC2);
                aT3 = fmaf(t3.x, fast_exp2(t3.y * e3.td), aT3);
                aC3 = fmaf(c3.x, fast_exp2(c3.y * e3.td), aC3);
            }
            for (; s < i; s += 4) {
                Ent e0 = sh[s];
                float2 t0 = ldh2(ttb + e0.ko);
                float2 c0 = ldh2(tcb + e0.co);
                aT0 = fmaf(t0.x, fast_exp2(t0.y * e0.td), aT0);
                aC0 = fmaf(c0.x, fast_exp2(c0.y * e0.td), aC0);
            }
            float fev = g_FEmb[ti * EMB + e];
            float acc = ((aT0 + aT1) + (aT2 + aT3))
                      + fev * ((aC0 + aC1) + (aC2 + aC3));
            float total = block_reduce_256(acc, sred);
            if (tid == 0 && t_i >= 0.f) {
                float lam = g_BA[ti] + g_FB[ti * NCA + lc] + total;
                partial = -(logf(lam + 1e-16f) + lam);
            }
        }
    }

    // ---- publish partial + grid-completion finalizer ----
    if (tid == 0) {
        g_part[bid] = partial;
        __threadfence();
        unsigned n = atomicAdd(&g_done, 1u);
        sh_last = (n == (unsigned)(MAIN_BLKS - 1)) ? 1 : 0;
        if (sh_last) __threadfence();
    }
    __syncthreads();
    if (sh_last) {
        double v = 0.0;
        for (int idx = tid; idx < MAIN_BLKS; idx += 256) v += (double)g_part[idx];
        #pragma unroll
        for (int o = 16; o; o >>= 1) v += __shfl_down_sync(0xffffffffu, v, o);
        if ((tid & 31) == 0) dred[tid >> 5] = v;
        __syncthreads();
        if (tid == 0) {
            double r = 0.0;
            #pragma unroll
            for (int w = 0; w < 8; w++) r += dred[w];
            float Tf = readT(Tp);
            for (int b2 = 0; b2 < BSZ; b2++) {
                int lcL = cats[b2 * SEQ + SEQ - 1];
                float tlast = times[b2 * SEQ + SEQ - 1];
                float t0 = times[b2 * SEQ];
                r += (double)((g_Sba + g_SFB[lcL]) * (Tf - tlast) + g_I0 * t0);
            }
            out[0] = (float)r;
            g_done = 0u;  // reset for next replay
        }
    }
}

extern "C" void kernel_launch(void* const* d_in, const int* in_sizes, int n_in,
                              void* d_out, int out_size) {
    const float* times = (const float*)d_in[0];
    const int* types = (const int*)d_in[1];
    const int* cats = (const int*)d_in[2];
    const void* Tp = d_in[3];
    const float* type_emb = (const float*)d_in[4];
    const float* cat_emb = (const float*)d_in[5];
    const float* a = (const float*)d_in[6];
    const float* b = (const float*)d_in[7];
    const float* A = (const float*)d_in[8];
    const float* P = (const float*)d_in[9];
    const float* Bm = (const float*)d_in[10];
    const float* Q = (const float*)d_in[11];
    float* out = (float*)d_out;

    k_prep<<<PREP_BLKS, 256>>>(type_emb, cat_emb, a, b, A, P, Bm, Q);
    k_main<<<MAIN_BLKS, 256>>>(times, types, cats, Tp, out);
}

// round 12
// speedup vs baseline: 1.3010x; 1.1184x over previous
#include <cuda_runtime.h>
#include <cuda_fp16.h>

// CEHawkesProcess — Hawkes NLL. 2 launches: parallel prep + main.
// fp16 tables + e-vectorized loads: one lane handles e=2*lane, 2*lane+1 via a
// single 8B LDG, so ONE 32-lane warp covers all 64 embedding dims per item.
// Halves LDG/LDS/issue per item; EX2 (MUFU floor) unchanged.
// Inputs (metadata order):
// 0 event_times f32[B*L], 1 event_types i32[B*L], 2 event_categories i32[B*L],
// 3 T (scalar), 4 type_emb f32[NT*E], 5 cat_emb f32[NC*E], 6 a f32[NT*E],
// 7 b f32[NC*E], 8 A f32[NT*NT*E], 9 P f32[NT*NT*E], 10 Bm f32[NC*NC*E],
// 11 Q f32[NC*NC*E].  Output: scalar f32.

namespace {
constexpr int NTY = 50;
constexpr int NCA = 20;
constexpr int EMB = 64;
constexpr int BSZ = 4;
constexpr int SEQ = 256;
constexpr float NL2E = -1.4426950408889634f;  // -log2(e)

constexpr int HT_BLKS = BSZ * NTY;                        // 200
constexpr int HC_BLKS = BSZ;                              // 4
constexpr int EV_BLKS = BSZ * SEQ;                        // 1024
constexpr int MAIN_BLKS = HT_BLKS + HC_BLKS + EV_BLKS;    // 1228

constexpr int TT_BLKS = (NTY * NTY + 15) / 16;            // 157
constexpr int TC_BLKS = (NCA * NCA + 15) / 16;            // 25
constexpr int FB_BLKS = (NTY * NCA + 7) / 8;              // 125
constexpr int BA_BLKS = (NTY + 7) / 8;                    // 7
constexpr int FE_BLKS = 4;
constexpr int PREP_BLKS = TT_BLKS + TC_BLKS + FB_BLKS + BA_BLKS + FE_BLKS + 1;  // 319
}

// Tables, [target][source][e], fp16-packed {w, r} per entry.
__device__ __half2 g_TTh[NTY * NTY * EMB];
__device__ __half2 g_TCh[NCA * NCA * EMB];
__device__ float g_FEmb[NTY * EMB];
__device__ float g_BA[NTY];
__device__ float g_SP[NTY];
__device__ float g_FB[NTY * NCA];
__device__ float g_Fsum[EMB];
__device__ float g_SFB[NCA];
__device__ float g_Sba, g_I0;
__device__ float g_part[MAIN_BLKS];
__device__ unsigned g_done;                // zero-init; finalizer resets (replay-safe)

struct alignas(16) Ent { float td; int ko; int co; int pad; };

__device__ __forceinline__ float fast_exp2(float x) {
    float r;
    asm("ex2.approx.ftz.f32 %0, %1;" : "=f"(r) : "f"(x));
    return r;
}

__device__ __forceinline__ float softplusf(float x) {
    return fmaxf(x, 0.f) + log1pf(expf(-fabsf(x)));
}

// T may arrive as int32 (value 128) or float32 bits; disambiguate.
__device__ __forceinline__ float readT(const void* p) {
    int v = *(const int*)p;
    return (v > 0 && v < (1 << 24)) ? (float)v : __int_as_float(v);
}

__device__ __forceinline__ float warp_reduce(float v) {
    #pragma unroll
    for (int o = 16; o; o >>= 1) v += __shfl_down_sync(0xffffffffu, v, o);
    return v;
}

__device__ __forceinline__ float block_reduce_256(float v, float* sred) {
    v = warp_reduce(v);
    int tid = threadIdx.x;
    if ((tid & 31) == 0) sred[tid >> 5] = v;
    __syncthreads();
    float r = 0.f;
    if (tid == 0) {
        #pragma unroll
        for (int w = 0; w < 8; w++) r += sred[w];
    }
    return r;
}

// Load 2 adjacent fp16 table entries (e=2*lane, 2*lane+1) in one 8B LDG.
struct EPair { float2 a; float2 b; };  // a = {w,r} for e0, b = {w,r} for e1
__device__ __forceinline__ EPair ld2h2(const __half2* p) {
    uint2 raw = __ldg((const uint2*)p);
    EPair r;
    r.a = __half22float2(*(__half2*)&raw.x);
    r.b = __half22float2(*(__half2*)&raw.y);
    return r;
}

// ======================= prep: tables + scalars + femb, all parallel =========
__global__ void __launch_bounds__(256) k_prep(
    const float* __restrict__ f, const float* __restrict__ g,
    const float* __restrict__ a, const float* __restrict__ b,
    const float* __restrict__ A, const float* __restrict__ P,
    const float* __restrict__ Bm, const float* __restrict__ Q) {
    int bid = blockIdx.x;
    int tid = threadIdx.x;

    if (bid < TT_BLKS) {
        int p = bid * 16 + (tid >> 4);          // p = t*NTY + k (write row)
        if (p < NTY * NTY) {
            int e = (tid & 15) << 2;
            int t = p / NTY, k = p - t * NTY;
            int rd = (k * NTY + t) * EMB + e;   // A/P stored [k][t][e]
            float4 Av = *(const float4*)(A + rd);
            float4 Pv = *(const float4*)(P + rd);
            float4 ft = *(const float4*)(f + t * EMB + e);
            float4 fk = *(const float4*)(f + k * EMB + e);
            float w0 = ft.x * fk.x, w1 = ft.y * fk.y;
            float w2 = ft.z * fk.z, w3 = ft.w * fk.w;
            __half2 h0 = __floats2half2_rn(w0 * Av.x, NL2E * w0 * Pv.x);
            __half2 h1 = __floats2half2_rn(w1 * Av.y, NL2E * w1 * Pv.y);
            __half2 h2 = __floats2half2_rn(w2 * Av.z, NL2E * w2 * Pv.z);
            __half2 h3 = __floats2half2_rn(w3 * Av.w, NL2E * w3 * Pv.w);
            uint4 pkt;
            pkt.x = *(unsigned*)&h0; pkt.y = *(unsigned*)&h1;
            pkt.z = *(unsigned*)&h2; pkt.w = *(unsigned*)&h3;
            *(uint4*)(g_TTh + p * EMB + e) = pkt;
        }
        return;
    }
    bid -= TT_BLKS;
    if (bid < TC_BLKS) {
        int p = bid * 16 + (tid >> 4);          // p = c2*NCA + c1 (write row)
        if (p < NCA * NCA) {
            int e = (tid & 15) << 2;
            int c2 = p / NCA, c1 = p - c2 * NCA;
            int rd = (c1 * NCA + c2) * EMB + e; // Bm/Q stored [c1][c2][e]
            float4 Bv = *(const float4*)(Bm + rd);
            float4 Qv = *(const float4*)(Q + rd);
            float4 g2 = *(const float4*)(g + c2 * EMB + e);
            float4 g1 = *(const float4*)(g + c1 * EMB + e);
            float w0 = g2.x * g1.x, w1 = g2.y * g1.y;
            float w2 = g2.z * g1.z, w3 = g2.w * g1.w;
            __half2 h0 = __floats2half2_rn(w0 * Bv.x, NL2E * w0 * Qv.x);
            __half2 h1 = __floats2half2_rn(w1 * Bv.y, NL2E * w1 * Qv.y);
            __half2 h2 = __floats2half2_rn(w2 * Bv.z, NL2E * w2 * Qv.z);
            __half2 h3 = __floats2half2_rn(w3 * Bv.w, NL2E * w3 * Qv.w);
            uint4 pkt;
            pkt.x = *(unsigned*)&h0; pkt.y = *(unsigned*)&h1;
            pkt.z = *(unsigned*)&h2; pkt.w = *(unsigned*)&h3;
            *(uint4*)(g_TCh + p * EMB + e) = pkt;
        }
        return;
    }
    bid -= TC_BLKS;
    if (bid < FB_BLKS) {
        int w = tid >> 5, lane = tid & 31;
        int idx = bid * 8 + w;
        if (idx < NTY * NCA) {
            int t = idx / NCA, c = idx - t * NCA;
            float s = f[t * EMB + lane] * b[c * EMB + lane]
                    + f[t * EMB + lane + 32] * b[c * EMB + lane + 32];
            s = warp_reduce(s);
            if (lane == 0) g_FB[idx] = s;
        }
        return;
    }
    bid -= FB_BLKS;
    if (bid < BA_BLKS) {
        int w = tid >> 5, lane = tid & 31;
        int t = bid * 8 + w;
        if (t < NTY) {
            float x0 = f[t * EMB + lane] * a[t * EMB + lane];
            float x1 = f[t * EMB + lane + 32] * a[t * EMB + lane + 32];
            float ba = warp_reduce(x0 + x1);
            float sp = warp_reduce(softplusf(x0) + softplusf(x1));
            if (lane == 0) { g_BA[t] = ba; g_SP[t] = sp; }
        }
        return;
    }
    bid -= BA_BLKS;
    if (bid < FE_BLKS) {
        int idx4 = bid * 256 + tid;
        if (idx4 < (NTY * EMB) / 4)
            ((float4*)g_FEmb)[idx4] = ((const float4*)f)[idx4];
        return;
    }
    // ---- final scalar block: Fsum, SFB, Sba, I0 ----
    __shared__ float fs_sh[EMB];
    __shared__ float sred1[8];
    __shared__ float sred2[8];
    if (tid < EMB) {
        float s = 0.f;
        #pragma unroll
        for (int t = 0; t < NTY; t++) s += f[t * EMB + tid];
        g_Fsum[tid] = s;
        fs_sh[tid] = s;
    }
    float sba = 0.f, i0 = 0.f;
    for (int idx = tid; idx < NTY * EMB; idx += 256) {
        float x = f[idx] * a[idx];
        sba += x;
        i0 += softplusf(x);
    }
    sba = warp_reduce(sba);
    i0 = warp_reduce(i0);
    if ((tid & 31) == 0) { sred1[tid >> 5] = sba; sred2[tid >> 5] = i0; }
    __syncthreads();
    if (tid == 0) {
        float s = 0.f, s2 = 0.f;
        #pragma unroll
        for (int w = 0; w < 8; w++) { s += sred1[w]; s2 += sred2[w]; }
        g_Sba = s;
        g_I0 = s2;
    }
    {
        int w = tid >> 5, lane = tid & 31;
        for (int c = w; c < NCA; c += 8) {
            float s = fs_sh[lane] * b[c * EMB + lane]
                    + fs_sh[lane + 32] * b[c * EMB + lane + 32];
            s = warp_reduce(s);
            if (lane == 0) g_SFB[c] = s;
        }
    }
}

// ======================= main: e-vectorized fp16-table scan ==================
__global__ void __launch_bounds__(256) k_main(
    const float* __restrict__ times, const int* __restrict__ types,
    const int* __restrict__ cats, const void* __restrict__ Tp,
    float* __restrict__ out) {
    int bid = blockIdx.x;
    int tid = threadIdx.x;
    __shared__ Ent sh[SEQ];
    __shared__ float sred[8];
    __shared__ double dred[8];
    __shared__ int sh_last;

    int lane = tid & 31;
    int ch = tid >> 5;          // 0..7 chunks; one warp covers all 64 e per item
    int e2 = lane << 1;         // this lane handles e2 and e2+1
    float partial = 0.f;

    if (bid < HT_BLKS) {
        // ---- horizon type channel: (b, t) ----
        int bb = bid / NTY;
        int t = bid - bb * NTY;
        float Tf = readT(Tp);
        const float* ts = times + bb * SEQ;
        const int* ty = types + bb * SEQ;
        float tlast = ts[SEQ - 1];
        for (int s = tid; s < SEQ; s += 256) {
            Ent en; en.td = Tf - ts[s]; en.ko = ty[s] * EMB; en.co = 0; en.pad = 0;
            sh[s] = en;
        }
        __syncthreads();
        const __half2* __restrict__ ttb = g_TTh + (size_t)t * (NTY * EMB) + e2;
        float a0 = 0.f, a1 = 0.f, a2 = 0.f, a3 = 0.f;
        #pragma unroll 2
        for (int s = ch; s < SEQ; s += 16) {
            Ent e0 = sh[s], e1 = sh[s + 8];
            EPair w0 = ld2h2(ttb + e0.ko);
            EPair w1 = ld2h2(ttb + e1.ko);
            a0 = fmaf(w0.a.x, fast_exp2(w0.a.y * e0.td), a0);
            a1 = fmaf(w0.b.x, fast_exp2(w0.b.y * e0.td), a1);
            a2 = fmaf(w1.a.x, fast_exp2(w1.a.y * e1.td), a2);
            a3 = fmaf(w1.b.x, fast_exp2(w1.b.y * e1.td), a3);
        }
        float total = block_reduce_256((a0 + a1) + (a2 + a3), sred);
        if (tid == 0) partial = total * (Tf - tlast);
    } else if (bid < HT_BLKS + HC_BLKS) {
        // ---- horizon category channel: b ----
        int bb = bid - HT_BLKS;
        float Tf = readT(Tp);
        const float* ts = times + bb * SEQ;
        const int* ct = cats + bb * SEQ;
        float tlast = ts[SEQ - 1];
        for (int s = tid; s < SEQ; s += 256) {
            Ent en; en.td = Tf - ts[s]; en.co = ct[s] * EMB; en.ko = 0; en.pad = 0;
            sh[s] = en;
        }
        __syncthreads();
        int lcL = ct[SEQ - 1];
        const __half2* __restrict__ tcb = g_TCh + (size_t)lcL * (NCA * EMB) + e2;
        float a0 = 0.f, a1 = 0.f, a2 = 0.f, a3 = 0.f;
        #pragma unroll 2
        for (int s = ch; s < SEQ; s += 16) {
            Ent e0 = sh[s], e1 = sh[s + 8];
            EPair w0 = ld2h2(tcb + e0.co);
            EPair w1 = ld2h2(tcb + e1.co);
            a0 = fmaf(w0.a.x, fast_exp2(w0.a.y * e0.td), a0);
            a1 = fmaf(w0.b.x, fast_exp2(w0.b.y * e0.td), a1);
            a2 = fmaf(w1.a.x, fast_exp2(w1.a.y * e1.td), a2);
            a3 = fmaf(w1.b.x, fast_exp2(w1.b.y * e1.td), a3);
        }
        float2 fsum = *(const float2*)(g_Fsum + e2);
        float acc = (a0 + a2) * fsum.x + (a1 + a3) * fsum.y;
        float total = block_reduce_256(acc, sred);
        if (tid == 0) partial = total * (Tf - tlast);
    } else {
        // ---- per-event log-likelihood (descending-i order; heaviest first) ----
        int local = bid - HT_BLKS - HC_BLKS;
        int i = (SEQ - 1) - (local >> 2);
        int bb = local & 3;
        const float* ts = times + bb * SEQ;
        const int* ty = types + bb * SEQ;
        const int* ct = cats + bb * SEQ;
        int ti = ty[i];
        float t_i = ts[i];

        if (i == 0) {
            if (tid == 0 && t_i >= 0.f) {
                float lam = g_SP[ti];
                partial = -(logf(lam + 1e-16f) + lam);
            }
        } else {
            for (int s = tid; s < i; s += 256) {
                Ent en;
                en.td = t_i - ts[s];
                en.ko = ty[s] * EMB;
                en.co = ct[s] * EMB;
                en.pad = 0;
                sh[s] = en;
            }
            __syncthreads();

            int lc = ct[i - 1];
            const __half2* __restrict__ ttb = g_TTh + (size_t)ti * (NTY * EMB) + e2;
            const __half2* __restrict__ tcb = g_TCh + (size_t)lc * (NCA * EMB) + e2;
            float aT0 = 0.f, aT1 = 0.f, aT2 = 0.f, aT3 = 0.f;
            float aC0 = 0.f, aC1 = 0.f, aC2 = 0.f, aC3 = 0.f;
            int s = ch;
            for (; s + 8 < i; s += 16) {
                Ent e0 = sh[s], e1 = sh[s + 8];
                EPair t0 = ld2h2(ttb + e0.ko);
                EPair c0 = ld2h2(tcb + e0.co);
                EPair t1 = ld2h2(ttb + e1.ko);
                EPair c1 = ld2h2(tcb + e1.co);
                aT0 = fmaf(t0.a.x, fast_exp2(t0.a.y * e0.td), aT0);
                aT1 = fmaf(t0.b.x, fast_exp2(t0.b.y * e0.td), aT1);
                aC0 = fmaf(c0.a.x, fast_exp2(c0.a.y * e0.td), aC0);
                aC1 = fmaf(c0.b.x, fast_exp2(c0.b.y * e0.td), aC1);
                aT2 = fmaf(t1.a.x, fast_exp2(t1.a.y * e1.td), aT2);
                aT3 = fmaf(t1.b.x, fast_exp2(t1.b.y * e1.td), aT3);
                aC2 = fmaf(c1.a.x, fast_exp2(c1.a.y * e1.td), aC2);
                aC3 = fmaf(c1.b.x, fast_exp2(c1.b.y * e1.td), aC3);
            }
            if (s < i) {
                Ent e0 = sh[s];
                EPair t0 = ld2h2(ttb + e0.ko);
                EPair c0 = ld2h2(tcb + e0.co);
                aT0 = fmaf(t0.a.x, fast_exp2(t0.a.y * e0.td), aT0);
                aT1 = fmaf(t0.b.x, fast_exp2(t0.b.y * e0.td), aT1);
                aC0 = fmaf(c0.a.x, fast_exp2(c0.a.y * e0.td), aC0);
                aC1 = fmaf(c0.b.x, fast_exp2(c0.b.y * e0.td), aC1);
            }
            float2 fev = *(const float2*)(g_FEmb + ti * EMB + e2);
            float acc = (aT0 + aT2) + fev.x * (aC0 + aC2)
                      + (aT1 + aT3) + fev.y * (aC1 + aC3);
            float total = block_reduce_256(acc, sred);
            if (tid == 0 && t_i >= 0.f) {
                float lam = g_BA[ti] + g_FB[ti * NCA + lc] + total;
                partial = -(logf(lam + 1e-16f) + lam);
            }
        }
    }

    // ---- publish partial + grid-completion finalizer ----
    if (tid == 0) {
        g_part[bid] = partial;
        __threadfence();
        unsigned n = atomicAdd(&g_done, 1u);
        sh_last = (n == (unsigned)(MAIN_BLKS - 1)) ? 1 : 0;
        if (sh_last) __threadfence();
    }
    __syncthreads();
    if (sh_last) {
        double v = 0.0;
        for (int idx = tid; idx < MAIN_BLKS; idx += 256) v += (double)g_part[idx];
        #pragma unroll
        for (int o = 16; o; o >>= 1) v += __shfl_down_sync(0xffffffffu, v, o);
        if ((tid & 31) == 0) dred[tid >> 5] = v;
        __syncthreads();
        if (tid == 0) {
            double r = 0.0;
            #pragma unroll
            for (int w = 0; w < 8; w++) r += dred[w];
            float Tf = readT(Tp);
            for (int b2 = 0; b2 < BSZ; b2++) {
                int lcL = cats[b2 * SEQ + SEQ - 1];
                float tlast = times[b2 * SEQ + SEQ - 1];
                float t0 = times[b2 * SEQ];
                r += (double)((g_Sba + g_SFB[lcL]) * (Tf - tlast) + g_I0 * t0);
            }
            out[0] = (float)r;
            g_done = 0u;  // reset for next replay
        }
    }
}

extern "C" void kernel_launch(void* const* d_in, const int* in_sizes, int n_in,
                              void* d_out, int out_size) {
    const float* times = (const float*)d_in[0];
    const int* types = (const int*)d_in[1];
    const int* cats = (const int*)d_in[2];
    const void* Tp = d_in[3];
    const float* type_emb = (const float*)d_in[4];
    const float* cat_emb = (const float*)d_in[5];
    const float* a = (const float*)d_in[6];
    const float* b = (const float*)d_in[7];
    const float* A = (const float*)d_in[8];
    const float* P = (const float*)d_in[9];
    const float* Bm = (const float*)d_in[10];
    const float* Q = (const float*)d_in[11];
    float* out = (float*)d_out;

    k_prep<<<PREP_BLKS, 256>>>(type_emb, cat_emb, a, b, A, P, Bm, Q);
    k_main<<<MAIN_BLKS, 256>>>(times, types, cats, Tp, out);
}

// round 13
// speedup vs baseline: 1.3735x; 1.0557x over previous
#include <cuda_runtime.h>
#include <cuda_fp16.h>

// CEHawkesProcess — Hawkes NLL. 2 launches: parallel prep + main.
// Tables packed {half2 w01, half2 r01} per lane-pair (one 8B LDG covers 2 e's);
// td baked in shared as broadcast half2. Inner loop per channel per item is
// HMUL2 -> ex2.approx.f16x2 (ONE MUFU op for 2 exps) -> HFMA2. f16x2
// accumulators hold <=16 signed ~1e-3 terms, flushed to f32 before reduce.
// Inputs (metadata order):
// 0 event_times f32[B*L], 1 event_types i32[B*L], 2 event_categories i32[B*L],
// 3 T (scalar), 4 type_emb f32[NT*E], 5 cat_emb f32[NC*E], 6 a f32[NT*E],
// 7 b f32[NC*E], 8 A f32[NT*NT*E], 9 P f32[NT*NT*E], 10 Bm f32[NC*NC*E],
// 11 Q f32[NC*NC*E].  Output: scalar f32.

namespace {
constexpr int NTY = 50;
constexpr int NCA = 20;
constexpr int EMB = 64;
constexpr int LP = EMB / 2;                 // lane-pairs per row = 32
constexpr int BSZ = 4;
constexpr int SEQ = 256;
constexpr float NL2E = -1.4426950408889634f;  // -log2(e)

constexpr int HT_BLKS = BSZ * NTY;                        // 200
constexpr int HC_BLKS = BSZ;                              // 4
constexpr int EV_BLKS = BSZ * SEQ;                        // 1024
constexpr int MAIN_BLKS = HT_BLKS + HC_BLKS + EV_BLKS;    // 1228

constexpr int TT_BLKS = (NTY * NTY + 15) / 16;            // 157
constexpr int TC_BLKS = (NCA * NCA + 15) / 16;            // 25
constexpr int FB_BLKS = (NTY * NCA + 7) / 8;              // 125
constexpr int BA_BLKS = (NTY + 7) / 8;                    // 7
constexpr int FE_BLKS = 4;
constexpr int PREP_BLKS = TT_BLKS + TC_BLKS + FB_BLKS + BA_BLKS + FE_BLKS + 1;  // 319
}

// Tables, [target][source][lanepair]: each uint2 = {half2{w_e0,w_e1}, half2{r_e0,r_e1}}.
__device__ uint2 g_TT2[NTY * NTY * LP];
__device__ uint2 g_TC2[NCA * NCA * LP];
__device__ float g_FEmb[NTY * EMB];
__device__ float g_BA[NTY];
__device__ float g_SP[NTY];
__device__ float g_FB[NTY * NCA];
__device__ float g_Fsum[EMB];
__device__ float g_SFB[NCA];
__device__ float g_Sba, g_I0;
__device__ float g_part[MAIN_BLKS];
__device__ unsigned g_done;                // zero-init; finalizer resets (replay-safe)

struct alignas(16) Ent { unsigned td2; int ko; int co; int pad; };

__device__ __forceinline__ __half2 fast_exp2_h2(__half2 x) {
    unsigned xi = *(unsigned*)&x;
    unsigned r;
    asm("ex2.approx.f16x2 %0, %1;" : "=r"(r) : "r"(xi));
    return *(__half2*)&r;
}

__device__ __forceinline__ float softplusf(float x) {
    return fmaxf(x, 0.f) + log1pf(expf(-fabsf(x)));
}

// T may arrive as int32 (value 128) or float32 bits; disambiguate.
__device__ __forceinline__ float readT(const void* p) {
    int v = *(const int*)p;
    return (v > 0 && v < (1 << 24)) ? (float)v : __int_as_float(v);
}

__device__ __forceinline__ float warp_reduce(float v) {
    #pragma unroll
    for (int o = 16; o; o >>= 1) v += __shfl_down_sync(0xffffffffu, v, o);
    return v;
}

__device__ __forceinline__ float block_reduce_256(float v, float* sred) {
    v = warp_reduce(v);
    int tid = threadIdx.x;
    if ((tid & 31) == 0) sred[tid >> 5] = v;
    __syncthreads();
    float r = 0.f;
    if (tid == 0) {
        #pragma unroll
        for (int w = 0; w < 8; w++) r += sred[w];
    }
    return r;
}

__device__ __forceinline__ unsigned td_to_h2(float td) {
    __half h = __float2half_rn(td);
    __half2 h2 = __half2half2(h);
    return *(unsigned*)&h2;
}

// ======================= prep: tables + scalars + femb, all parallel =========
__global__ void __launch_bounds__(256) k_prep(
    const float* __restrict__ f, const float* __restrict__ g,
    const float* __restrict__ a, const float* __restrict__ b,
    const float* __restrict__ A, const float* __restrict__ P,
    const float* __restrict__ Bm, const float* __restrict__ Q) {
    int bid = blockIdx.x;
    int tid = threadIdx.x;

    if (bid < TT_BLKS) {
        int p = bid * 16 + (tid >> 4);          // p = t*NTY + k (write row)
        if (p < NTY * NTY) {
            int e = (tid & 15) << 2;            // e, e+1, e+2, e+3
            int t = p / NTY, k = p - t * NTY;
            int rd = (k * NTY + t) * EMB + e;   // A/P stored [k][t][e]
            float4 Av = *(const float4*)(A + rd);
            float4 Pv = *(const float4*)(P + rd);
            float4 ft = *(const float4*)(f + t * EMB + e);
            float4 fk = *(const float4*)(f + k * EMB + e);
            float w0 = ft.x * fk.x, w1 = ft.y * fk.y;
            float w2 = ft.z * fk.z, w3 = ft.w * fk.w;
            __half2 hw01 = __floats2half2_rn(w0 * Av.x, w1 * Av.y);
            __half2 hr01 = __floats2half2_rn(NL2E * w0 * Pv.x, NL2E * w1 * Pv.y);
            __half2 hw23 = __floats2half2_rn(w2 * Av.z, w3 * Av.w);
            __half2 hr23 = __floats2half2_rn(NL2E * w2 * Pv.z, NL2E * w3 * Pv.w);
            uint4 pkt;
            pkt.x = *(unsigned*)&hw01; pkt.y = *(unsigned*)&hr01;
            pkt.z = *(unsigned*)&hw23; pkt.w = *(unsigned*)&hr23;
            *(uint4*)(g_TT2 + p * LP + (e >> 1)) = pkt;
        }
        return;
    }
    bid -= TT_BLKS;
    if (bid < TC_BLKS) {
        int p = bid * 16 + (tid >> 4);          // p = c2*NCA + c1 (write row)
        if (p < NCA * NCA) {
            int e = (tid & 15) << 2;
            int c2 = p / NCA, c1 = p - c2 * NCA;
            int rd = (c1 * NCA + c2) * EMB + e; // Bm/Q stored [c1][c2][e]
            float4 Bv = *(const float4*)(Bm + rd);
            float4 Qv = *(const float4*)(Q + rd);
            float4 g2 = *(const float4*)(g + c2 * EMB + e);
            float4 g1 = *(const float4*)(g + c1 * EMB + e);
            float w0 = g2.x * g1.x, w1 = g2.y * g1.y;
            float w2 = g2.z * g1.z, w3 = g2.w * g1.w;
            __half2 hw01 = __floats2half2_rn(w0 * Bv.x, w1 * Bv.y);
            __half2 hr01 = __floats2half2_rn(NL2E * w0 * Qv.x, NL2E * w1 * Qv.y);
            __half2 hw23 = __floats2half2_rn(w2 * Bv.z, w3 * Bv.w);
            __half2 hr23 = __floats2half2_rn(NL2E * w2 * Qv.z, NL2E * w3 * Qv.w);
            uint4 pkt;
            pkt.x = *(unsigned*)&hw01; pkt.y = *(unsigned*)&hr01;
            pkt.z = *(unsigned*)&hw23; pkt.w = *(unsigned*)&hr23;
            *(uint4*)(g_TC2 + p * LP + (e >> 1)) = pkt;
        }
        return;
    }
    bid -= TC_BLKS;
    if (bid < FB_BLKS) {
        int w = tid >> 5, lane = tid & 31;
        int idx = bid * 8 + w;
        if (idx < NTY * NCA) {
            int t = idx / NCA, c = idx - t * NCA;
            float s = f[t * EMB + lane] * b[c * EMB + lane]
                    + f[t * EMB + lane + 32] * b[c * EMB + lane + 32];
            s = warp_reduce(s);
            if (lane == 0) g_FB[idx] = s;
        }
        return;
    }
    bid -= FB_BLKS;
    if (bid < BA_BLKS) {
        int w = tid >> 5, lane = tid & 31;
        int t = bid * 8 + w;
        if (t < NTY) {
            float x0 = f[t * EMB + lane] * a[t * EMB + lane];
            float x1 = f[t * EMB + lane + 32] * a[t * EMB + lane + 32];
            float ba = warp_reduce(x0 + x1);
            float sp = warp_reduce(softplusf(x0) + softplusf(x1));
            if (lane == 0) { g_BA[t] = ba; g_SP[t] = sp; }
        }
        return;
    }
    bid -= BA_BLKS;
    if (bid < FE_BLKS) {
        int idx4 = bid * 256 + tid;
        if (idx4 < (NTY * EMB) / 4)
            ((float4*)g_FEmb)[idx4] = ((const float4*)f)[idx4];
        return;
    }
    // ---- final scalar block: Fsum, SFB, Sba, I0 ----
    __shared__ float fs_sh[EMB];
    __shared__ float sred1[8];
    __shared__ float sred2[8];
    if (tid < EMB) {
        float s = 0.f;
        #pragma unroll
        for (int t = 0; t < NTY; t++) s += f[t * EMB + tid];
        g_Fsum[tid] = s;
        fs_sh[tid] = s;
    }
    float sba = 0.f, i0 = 0.f;
    for (int idx = tid; idx < NTY * EMB; idx += 256) {
        float x = f[idx] * a[idx];
        sba += x;
        i0 += softplusf(x);
    }
    sba = warp_reduce(sba);
    i0 = warp_reduce(i0);
    if ((tid & 31) == 0) { sred1[tid >> 5] = sba; sred2[tid >> 5] = i0; }
    __syncthreads();
    if (tid == 0) {
        float s = 0.f, s2 = 0.f;
        #pragma unroll
        for (int w = 0; w < 8; w++) { s += sred1[w]; s2 += sred2[w]; }
        g_Sba = s;
        g_I0 = s2;
    }
    {
        int w = tid >> 5, lane = tid & 31;
        for (int c = w; c < NCA; c += 8) {
            float s = fs_sh[lane] * b[c * EMB + lane]
                    + fs_sh[lane + 32] * b[c * EMB + lane + 32];
            s = warp_reduce(s);
            if (lane == 0) g_SFB[c] = s;
        }
    }
}

// ======================= main: f16x2 exp pipeline ============================
__global__ void __launch_bounds__(256) k_main(
    const float* __restrict__ times, const int* __restrict__ types,
    const int* __restrict__ cats, const void* __restrict__ Tp,
    float* __restrict__ out) {
    int bid = blockIdx.x;
    int tid = threadIdx.x;
    __shared__ Ent sh[SEQ];
    __shared__ float sred[8];
    __shared__ double dred[8];
    __shared__ int sh_last;

    int lane = tid & 31;
    int ch = tid >> 5;          // 0..7 chunks; one warp covers all 64 e per item
    float partial = 0.f;
    const __half2 hz = __float2half2_rn(0.f);

    if (bid < HT_BLKS) {
        // ---- horizon type channel: (b, t) ----
        int bb = bid / NTY;
        int t = bid - bb * NTY;
        float Tf = readT(Tp);
        const float* ts = times + bb * SEQ;
        const int* ty = types + bb * SEQ;
        float tlast = ts[SEQ - 1];
        for (int s = tid; s < SEQ; s += 256) {
            Ent en; en.td2 = td_to_h2(Tf - ts[s]); en.ko = ty[s] * LP; en.co = 0; en.pad = 0;
            sh[s] = en;
        }
        __syncthreads();
        const uint2* __restrict__ ttb = g_TT2 + (size_t)t * (NTY * LP) + lane;
        __half2 a0 = hz, a1 = hz;
        #pragma unroll 2
        for (int s = ch; s < SEQ; s += 16) {
            Ent e0 = sh[s], e1 = sh[s + 8];
            uint2 r0 = __ldg(ttb + e0.ko);
            uint2 r1 = __ldg(ttb + e1.ko);
            __half2 x0 = __hmul2(*(__half2*)&r0.y, *(__half2*)&e0.td2);
            __half2 x1 = __hmul2(*(__half2*)&r1.y, *(__half2*)&e1.td2);
            a0 = __hfma2(*(__half2*)&r0.x, fast_exp2_h2(x0), a0);
            a1 = __hfma2(*(__half2*)&r1.x, fast_exp2_h2(x1), a1);
        }
        float2 f0 = __half22float2(a0);
        float2 f1 = __half22float2(a1);
        float total = block_reduce_256((f0.x + f0.y) + (f1.x + f1.y), sred);
        if (tid == 0) partial = total * (Tf - tlast);
    } else if (bid < HT_BLKS + HC_BLKS) {
        // ---- horizon category channel: b ----
        int bb = bid - HT_BLKS;
        float Tf = readT(Tp);
        const float* ts = times + bb * SEQ;
        const int* ct = cats + bb * SEQ;
        float tlast = ts[SEQ - 1];
        for (int s = tid; s < SEQ; s += 256) {
            Ent en; en.td2 = td_to_h2(Tf - ts[s]); en.co = ct[s] * LP; en.ko = 0; en.pad = 0;
            sh[s] = en;
        }
        __syncthreads();
        int lcL = ct[SEQ - 1];
        const uint2* __restrict__ tcb = g_TC2 + (size_t)lcL * (NCA * LP) + lane;
        __half2 a0 = hz, a1 = hz;
        #pragma unroll 2
        for (int s = ch; s < SEQ; s += 16) {
            Ent e0 = sh[s], e1 = sh[s + 8];
            uint2 r0 = __ldg(tcb + e0.co);
            uint2 r1 = __ldg(tcb + e1.co);
            __half2 x0 = __hmul2(*(__half2*)&r0.y, *(__half2*)&e0.td2);
            __half2 x1 = __hmul2(*(__half2*)&r1.y, *(__half2*)&e1.td2);
            a0 = __hfma2(*(__half2*)&r0.x, fast_exp2_h2(x0), a0);
            a1 = __hfma2(*(__half2*)&r1.x, fast_exp2_h2(x1), a1);
        }
        float2 f0 = __half22float2(a0);
        float2 f1 = __half22float2(a1);
        float2 fsum = *(const float2*)(g_Fsum + lane * 2);
        float acc = (f0.x + f1.x) * fsum.x + (f0.y + f1.y) * fsum.y;
        float total = block_reduce_256(acc, sred);
        if (tid == 0) partial = total * (Tf - tlast);
    } else {
        // ---- per-event log-likelihood (descending-i order; heaviest first) ----
        int local = bid - HT_BLKS - HC_BLKS;
        int i = (SEQ - 1) - (local >> 2);
        int bb = local & 3;
        const float* ts = times + bb * SEQ;
        const int* ty = types + bb * SEQ;
        const int* ct = cats + bb * SEQ;
        int ti = ty[i];
        float t_i = ts[i];

        if (i == 0) {
            if (tid == 0 && t_i >= 0.f) {
                float lam = g_SP[ti];
                partial = -(logf(lam + 1e-16f) + lam);
            }
        } else {
            for (int s = tid; s < i; s += 256) {
                Ent en;
                en.td2 = td_to_h2(t_i - ts[s]);
                en.ko = ty[s] * LP;
                en.co = ct[s] * LP;
                en.pad = 0;
                sh[s] = en;
            }
            __syncthreads();

            int lc = ct[i - 1];
            const uint2* __restrict__ ttb = g_TT2 + (size_t)ti * (NTY * LP) + lane;
            const uint2* __restrict__ tcb = g_TC2 + (size_t)lc * (NCA * LP) + lane;
            __half2 aT0 = hz, aT1 = hz, aC0 = hz, aC1 = hz;
            int s = ch;
            for (; s + 8 < i; s += 16) {
                Ent e0 = sh[s], e1 = sh[s + 8];
                uint2 t0 = __ldg(ttb + e0.ko);
                uint2 c0 = __ldg(tcb + e0.co);
                uint2 t1 = __ldg(ttb + e1.ko);
                uint2 c1 = __ldg(tcb + e1.co);
                __half2 td0 = *(__half2*)&e0.td2;
                __half2 td1 = *(__half2*)&e1.td2;
                __half2 xT0 = __hmul2(*(__half2*)&t0.y, td0);
                __half2 xC0 = __hmul2(*(__half2*)&c0.y, td0);
                __half2 xT1 = __hmul2(*(__half2*)&t1.y, td1);
                __half2 xC1 = __hmul2(*(__half2*)&c1.y, td1);
                aT0 = __hfma2(*(__half2*)&t0.x, fast_exp2_h2(xT0), aT0);
                aC0 = __hfma2(*(__half2*)&c0.x, fast_exp2_h2(xC0), aC0);
                aT1 = __hfma2(*(__half2*)&t1.x, fast_exp2_h2(xT1), aT1);
                aC1 = __hfma2(*(__half2*)&c1.x, fast_exp2_h2(xC1), aC1);
            }
            if (s < i) {
                Ent e0 = sh[s];
                uint2 t0 = __ldg(ttb + e0.ko);
                uint2 c0 = __ldg(tcb + e0.co);
                __half2 td0 = *(__half2*)&e0.td2;
                __half2 xT0 = __hmul2(*(__half2*)&t0.y, td0);
                __half2 xC0 = __hmul2(*(__half2*)&c0.y, td0);
                aT0 = __hfma2(*(__half2*)&t0.x, fast_exp2_h2(xT0), aT0);
                aC0 = __hfma2(*(__half2*)&c0.x, fast_exp2_h2(xC0), aC0);
            }
            float2 fT0 = __half22float2(aT0);
            float2 fT1 = __half22float2(aT1);
            float2 fC0 = __half22float2(aC0);
            float2 fC1 = __half22float2(aC1);
            float2 fev = *(const float2*)(g_FEmb + ti * EMB + lane * 2);
            float acc = (fT0.x + fT1.x) + fev.x * (fC0.x + fC1.x)
                      + (fT0.y + fT1.y) + fev.y * (fC0.y + fC1.y);
            float total = block_reduce_256(acc, sred);
            if (tid == 0 && t_i >= 0.f) {
                float lam = g_BA[ti] + g_FB[ti * NCA + lc] + total;
                partial = -(logf(lam + 1e-16f) + lam);
            }
        }
    }

    // ---- publish partial + grid-completion finalizer ----
    if (tid == 0) {
        g_part[bid] = partial;
        __threadfence();
        unsigned n = atomicAdd(&g_done, 1u);
        sh_last = (n == (unsigned)(MAIN_BLKS - 1)) ? 1 : 0;
        if (sh_last) __threadfence();
    }
    __syncthreads();
    if (sh_last) {
        double v = 0.0;
        for (int idx = tid; idx < MAIN_BLKS; idx += 256) v += (double)g_part[idx];
        #pragma unroll
        for (int o = 16; o; o >>= 1) v += __shfl_down_sync(0xffffffffu, v, o);
        if ((tid & 31) == 0) dred[tid >> 5] = v;
        __syncthreads();
        if (tid == 0) {
            double r = 0.0;
            #pragma unroll
            for (int w = 0; w < 8; w++) r += dred[w];
            float Tf = readT(Tp);
            for (int b2 = 0; b2 < BSZ; b2++) {
                int lcL = cats[b2 * SEQ + SEQ - 1];
                float tlast = times[b2 * SEQ + SEQ - 1];
                float t0 = times[b2 * SEQ];
                r += (double)((g_Sba + g_SFB[lcL]) * (Tf - tlast) + g_I0 * t0);
            }
            out[0] = (float)r;
            g_done = 0u;  // reset for next replay
        }
    }
}

extern "C" void kernel_launch(void* const* d_in, const int* in_sizes, int n_in,
                              void* d_out, int out_size) {
    const float* times = (const float*)d_in[0];
    const int* types = (const int*)d_in[1];
    const int* cats = (const int*)d_in[2];
    const void* Tp = d_in[3];
    const float* type_emb = (const float*)d_in[4];
    const float* cat_emb = (const float*)d_in[5];
    const float* a = (const float*)d_in[6];
    const float* b = (const float*)d_in[7];
    const float* A = (const float*)d_in[8];
    const float* P = (const float*)d_in[9];
    const float* Bm = (const float*)d_in[10];
    const float* Q = (const float*)d_in[11];
    float* out = (float*)d_out;

    k_prep<<<PREP_BLKS, 256>>>(type_emb, cat_emb, a, b, A, P, Bm, Q);
    k_main<<<MAIN_BLKS, 256>>>(times, types, cats, Tp, out);
}